// round 12
// baseline (speedup 1.0000x reference)
#include <cuda_runtime.h>
#include <cuda_fp16.h>
#include <cstdint>

// GGNN message passing (SIMT mma.sync; tcgen05 not available on sm_103 target).
// Stage1 (tf32 MMA): G[j,dir,c,d] = sum_e h[j,e]*W[dir,c,d,e]; fp16x2 blob
//   [b][dir][ch][kp][pd]: ch=j>>4, kp=(j&15)*2+a, word=(G_{c=2a}[d], G_{c=2a+1}[d]),
//   pd = (d&7)*8+(d>>3).  Block per (mtile, p4=dir*2+a); W transposed in-kernel.
// Stage2 (fp16 m16n8k16): out[b,i,dir*64+d] = sum_{j,c} 1[adjX==c]*G + bias.
//   dir=0: adjX=adj[b,i,j]; dir=1: adjX=adj[b,j,i]. One-hot A in regs (exact).
//   3-buffer cp.async pipeline, prefetch depth 2, one barrier per chunk.

__device__ uint32_t g_scratch[(size_t)8388608];  // 32 MB blob (f16x2 words)

__device__ __forceinline__ uint32_t f2tf(float x) {
    uint32_t r; asm("cvt.rna.tf32.f32 %0, %1;" : "=r"(r) : "f"(x)); return r;
}
__device__ __forceinline__ uint32_t pkh2(float lo, float hi) {
    __half2 p = __floats2half2_rn(lo, hi); return *(uint32_t*)&p;
}
__device__ __forceinline__ void mma8_tf32(float* d, uint32_t a0, uint32_t a1,
                                          uint32_t a2, uint32_t a3, uint32_t b0, uint32_t b1) {
    asm volatile("mma.sync.aligned.m16n8k8.row.col.f32.tf32.tf32.f32 "
                 "{%0,%1,%2,%3}, {%4,%5,%6,%7}, {%8,%9}, {%0,%1,%2,%3};"
                 : "+f"(d[0]), "+f"(d[1]), "+f"(d[2]), "+f"(d[3])
                 : "r"(a0), "r"(a1), "r"(a2), "r"(a3), "r"(b0), "r"(b1));
}
__device__ __forceinline__ void mma16_f16(float* d, uint32_t a0, uint32_t a1,
                                          uint32_t a2, uint32_t a3, uint32_t b0, uint32_t b1) {
    asm volatile("mma.sync.aligned.m16n8k16.row.col.f32.f16.f16.f32 "
                 "{%0,%1,%2,%3}, {%4,%5,%6,%7}, {%8,%9}, {%0,%1,%2,%3};"
                 : "+f"(d[0]), "+f"(d[1]), "+f"(d[2]), "+f"(d[3])
                 : "r"(a0), "r"(a1), "r"(a2), "r"(a3), "r"(b0), "r"(b1));
}
__device__ __forceinline__ void cpa16(uint32_t daddr, const void* gaddr) {
    asm volatile("cp.async.cg.shared.global [%0], [%1], 16;" :: "r"(daddr), "l"(gaddr));
}
__device__ __forceinline__ void cpa_commit() {
    asm volatile("cp.async.commit_group;" ::: "memory");
}
template <int N>
__device__ __forceinline__ void cpa_wait() {
    asm volatile("cp.async.wait_group %0;" :: "n"(N) : "memory");
}

// ---------------------------------------------------------------------------
// Stage 1: grid 2048 = (512 mtiles x 4 p4), 128 thr.
// smem: hs[64*68] + ws[64*136] = 13056 words = 52.2 KB.
// ---------------------------------------------------------------------------
#define S1_SMEM_W (4352 + 8704)

__global__ __launch_bounds__(128) void ggnn_stage1(const float* __restrict__ h,
                                                   const float* __restrict__ Win,
                                                   const float* __restrict__ Wout) {
    extern __shared__ uint32_t s1[];
    uint32_t* hs = s1;            // [row][e] stride 68
    uint32_t* ws = s1 + 4352;     // [e][n] stride 136

    const int bx = blockIdx.x;
    const int mtile = bx >> 2, p4 = bx & 3;
    const int t = threadIdx.x;
    const int warp = t >> 5, lane = t & 31;
    const int g = lane >> 2, tig = lane & 3;
    const int r0 = warp * 16 + g;

    // transpose W slice in-kernel: ws[e][n=t] = tf32(W[c][d][e]),
    // c = 2*(p4&1) + (t>>6), d = t&63
    {
        const float* Wd = (p4 & 2) ? Wout : Win;
        const float4* src = (const float4*)(Wd + (size_t)(p4 & 1) * 8192
                                            + (t >> 6) * 4096 + (t & 63) * 64);
#pragma unroll
        for (int i = 0; i < 16; i++) {
            float4 v = src[i];
            int e = 4 * i;
            ws[(e + 0) * 136 + t] = f2tf(v.x);
            ws[(e + 1) * 136 + t] = f2tf(v.y);
            ws[(e + 2) * 136 + t] = f2tf(v.z);
            ws[(e + 3) * 136 + t] = f2tf(v.w);
        }
    }
    // stage h tile (convert to tf32 bits)
    const float* hbase = h + (size_t)mtile * 4096;
#pragma unroll
    for (int q = 0; q < 8; q++) {
        int f4 = t + q * 128;
        int row = f4 >> 4, e4 = (f4 & 15) * 4;
        float4 v = *(const float4*)(hbase + row * 64 + e4);
        uint4 u = make_uint4(f2tf(v.x), f2tf(v.y), f2tf(v.z), f2tf(v.w));
        *(uint4*)(hs + row * 68 + e4) = u;
    }
    __syncthreads();

    float acc[16][4];
#pragma unroll
    for (int nt = 0; nt < 16; nt++)
#pragma unroll
        for (int k = 0; k < 4; k++) acc[nt][k] = 0.f;

#pragma unroll
    for (int ks = 0; ks < 8; ks++) {
        int e0 = ks * 8;
        uint32_t a0 = hs[r0 * 68 + e0 + tig];
        uint32_t a1 = hs[(r0 + 8) * 68 + e0 + tig];
        uint32_t a2 = hs[r0 * 68 + e0 + tig + 4];
        uint32_t a3 = hs[(r0 + 8) * 68 + e0 + tig + 4];
#pragma unroll
        for (int nt = 0; nt < 16; nt++) {
            uint32_t b0 = ws[(e0 + tig) * 136 + nt * 8 + g];
            uint32_t b1 = ws[(e0 + tig + 4) * 136 + nt * 8 + g];
            mma8_tf32(acc[nt], a0, a1, a2, a3, b0, b1);
        }
    }

    // blob store: word [ch][kp][pd], pd = 16*tig + half*8 + nt
    const int b = mtile >> 4;
    const int ch = (mtile & 15) * 4 + warp;
    const int dir = p4 >> 1, a = p4 & 1;
    uint32_t* blob = g_scratch + ((size_t)(b * 2 + dir) << 17);
#pragma unroll
    for (int rb2 = 0; rb2 < 2; rb2++) {      // rows g, g+8
        int kp = 2 * (g + 8 * rb2) + a;
        uint32_t* dst = blob + ch * 2048 + kp * 64 + 16 * tig;
        int i0 = rb2 * 2;
#pragma unroll
        for (int half = 0; half < 2; half++) {
#pragma unroll
            for (int grp = 0; grp < 2; grp++) {
                uint4 u;
                u.x = pkh2(acc[grp * 4 + 0][i0 + half], acc[grp * 4 + 8][i0 + half]);
                u.y = pkh2(acc[grp * 4 + 1][i0 + half], acc[grp * 4 + 9][i0 + half]);
                u.z = pkh2(acc[grp * 4 + 2][i0 + half], acc[grp * 4 + 10][i0 + half]);
                u.w = pkh2(acc[grp * 4 + 3][i0 + half], acc[grp * 4 + 11][i0 + half]);
                *(uint4*)(dst + half * 8 + grp * 4) = u;
            }
        }
    }
}

// ---------------------------------------------------------------------------
// Stage 2: grid (8 mtiles, 2 dirs, 32 b), 128 thr (4 warps x 32 rows), fp16 MMA.
// 3 buffers x (gs 32x68 + adj 2560) = 14208 words = 56.8 KB dynamic smem.
// ---------------------------------------------------------------------------
#define GS2_W (32 * 68)                  // 2176
#define AS2_W 2560
#define BUF2_W (GS2_W + AS2_W)           // 4736
#define SM2_W (3 * BUF2_W)               // 14208 words = 56832 B

template <int DIR>
__device__ __forceinline__ void stage2_impl(uint32_t* sm,
                                            const int* __restrict__ adj,
                                            const float* __restrict__ bias,
                                            float* __restrict__ out) {
    const int mtile = blockIdx.x;
    const int b     = blockIdx.z;
    const int t = threadIdx.x;
    const int warp = t >> 5, lane = t & 31;
    const int g = lane >> 2, tig = lane & 3;
    const int mbase = mtile * 128;
    const int rw = warp * 32;
    const int ca = 2 * (tig & 1);

    const uint32_t* blob = g_scratch + ((size_t)(b * 2 + DIR) << 17);
    const int* adjb = adj + (size_t)b * 1048576;

    float acc[2][8][4];
#pragma unroll
    for (int rb = 0; rb < 2; rb++)
#pragma unroll
        for (int nt = 0; nt < 8; nt++)
#pragma unroll
            for (int k = 0; k < 4; k++) acc[rb][nt][k] = 0.f;

    auto issue = [&](int ch, int buf) {
        const int j0 = ch * 16;
        uint32_t gdst = (uint32_t)__cvta_generic_to_shared(sm + buf * BUF2_W);
        uint32_t adst = gdst + GS2_W * 4;
        const uint32_t* gsrc = blob + (size_t)ch * 2048;
#pragma unroll
        for (int q = 0; q < 4; q++) {            // 512 u4s of G
            int idx = t + q * 128;
            int kp = idx >> 4, pd4 = (idx & 15) * 4;
            cpa16(gdst + (kp * 68 + pd4) * 4, gsrc + kp * 64 + pd4);
        }
        if constexpr (DIR == 0) {                // [r][jj] stride 20
#pragma unroll
            for (int q = 0; q < 4; q++) {
                int idx = t + q * 128;
                int r = idx >> 2, c4 = (idx & 3) * 4;
                cpa16(adst + (r * 20 + c4) * 4, adjb + (size_t)(mbase + r) * 1024 + j0 + c4);
            }
        } else {                                 // [jj][r] stride 136
#pragma unroll
            for (int q = 0; q < 4; q++) {
                int idx = t + q * 128;
                int jj = idx >> 5, r4 = (idx & 31) * 4;
                cpa16(adst + (jj * 136 + r4) * 4, adjb + (size_t)(j0 + jj) * 1024 + mbase + r4);
            }
        }
        cpa_commit();
    };

    issue(0, 0);
    issue(1, 1);

#pragma unroll 1
    for (int ch = 0; ch < 64; ch++) {
        if (ch < 63) cpa_wait<1>();
        else         cpa_wait<0>();
        __syncthreads();   // group ch complete everywhere; buf (ch+2)%3 free to refill

        if (ch < 62) issue(ch + 2, (ch + 2) % 3);

        const uint32_t* gs = sm + (ch % 3) * BUF2_W;
        const int* as_ = (const int*)(gs + GS2_W);
        constexpr int RS = DIR ? 1 : 20;
        constexpr int JS = DIR ? 136 : 1;

#pragma unroll
        for (int ks = 0; ks < 4; ks++) {
            const int jj0 = 4 * ks + (tig >> 1);
            int v00 = as_[(rw + g) * RS + jj0 * JS];
            int v01 = as_[(rw + g + 8) * RS + jj0 * JS];
            int v02 = as_[(rw + g) * RS + (jj0 + 2) * JS];
            int v03 = as_[(rw + g + 8) * RS + (jj0 + 2) * JS];
            int v10 = as_[(rw + g + 16) * RS + jj0 * JS];
            int v11 = as_[(rw + g + 24) * RS + jj0 * JS];
            int v12 = as_[(rw + g + 16) * RS + (jj0 + 2) * JS];
            int v13 = as_[(rw + g + 24) * RS + (jj0 + 2) * JS];
            uint32_t a00 = (v00 == ca) ? 0x3C00u : ((v00 == ca + 1) ? 0x3C000000u : 0u);
            uint32_t a01 = (v01 == ca) ? 0x3C00u : ((v01 == ca + 1) ? 0x3C000000u : 0u);
            uint32_t a02 = (v02 == ca) ? 0x3C00u : ((v02 == ca + 1) ? 0x3C000000u : 0u);
            uint32_t a03 = (v03 == ca) ? 0x3C00u : ((v03 == ca + 1) ? 0x3C000000u : 0u);
            uint32_t a10 = (v10 == ca) ? 0x3C00u : ((v10 == ca + 1) ? 0x3C000000u : 0u);
            uint32_t a11 = (v11 == ca) ? 0x3C00u : ((v11 == ca + 1) ? 0x3C000000u : 0u);
            uint32_t a12 = (v12 == ca) ? 0x3C00u : ((v12 == ca + 1) ? 0x3C000000u : 0u);
            uint32_t a13 = (v13 == ca) ? 0x3C00u : ((v13 == ca + 1) ? 0x3C000000u : 0u);

            const uint32_t* bp0 = gs + (8 * ks + tig) * 68 + 8 * g;
            const uint32_t* bp1 = bp0 + 4 * 68;
            uint4 B0a = *(const uint4*)(bp0);
            uint4 B0b = *(const uint4*)(bp0 + 4);
            uint4 B1a = *(const uint4*)(bp1);
            uint4 B1b = *(const uint4*)(bp1 + 4);

            mma16_f16(acc[0][0], a00, a01, a02, a03, B0a.x, B1a.x);
            mma16_f16(acc[0][1], a00, a01, a02, a03, B0a.y, B1a.y);
            mma16_f16(acc[0][2], a00, a01, a02, a03, B0a.z, B1a.z);
            mma16_f16(acc[0][3], a00, a01, a02, a03, B0a.w, B1a.w);
            mma16_f16(acc[0][4], a00, a01, a02, a03, B0b.x, B1b.x);
            mma16_f16(acc[0][5], a00, a01, a02, a03, B0b.y, B1b.y);
            mma16_f16(acc[0][6], a00, a01, a02, a03, B0b.z, B1b.z);
            mma16_f16(acc[0][7], a00, a01, a02, a03, B0b.w, B1b.w);
            mma16_f16(acc[1][0], a10, a11, a12, a13, B0a.x, B1a.x);
            mma16_f16(acc[1][1], a10, a11, a12, a13, B0a.y, B1a.y);
            mma16_f16(acc[1][2], a10, a11, a12, a13, B0a.z, B1a.z);
            mma16_f16(acc[1][3], a10, a11, a12, a13, B0a.w, B1a.w);
            mma16_f16(acc[1][4], a10, a11, a12, a13, B0b.x, B1b.x);
            mma16_f16(acc[1][5], a10, a11, a12, a13, B0b.y, B1b.y);
            mma16_f16(acc[1][6], a10, a11, a12, a13, B0b.z, B1b.z);
            mma16_f16(acc[1][7], a10, a11, a12, a13, B0b.w, B1b.w);
        }
    }

#pragma unroll
    for (int rb = 0; rb < 2; rb++) {
        const int i0 = mbase + rw + rb * 16 + g;
#pragma unroll
        for (int nt = 0; nt < 8; nt++) {
            int n = DIR * 64 + nt * 8 + tig * 2;
            float2 bv = *(const float2*)(bias + n);
            float* o0 = out + ((size_t)b * 1024 + i0) * 128 + n;
            float* o1 = out + ((size_t)b * 1024 + i0 + 8) * 128 + n;
            *(float2*)o0 = make_float2(acc[rb][nt][0] + bv.x, acc[rb][nt][1] + bv.y);
            *(float2*)o1 = make_float2(acc[rb][nt][2] + bv.x, acc[rb][nt][3] + bv.y);
        }
    }
}

__global__ __launch_bounds__(128) void ggnn_stage2(const int* __restrict__ adj,
                                                   const float* __restrict__ bias,
                                                   float* __restrict__ out) {
    extern __shared__ uint32_t sm[];
    if (blockIdx.y == 0) stage2_impl<0>(sm, adj, bias, out);
    else                 stage2_impl<1>(sm, adj, bias, out);
}

extern "C" void kernel_launch(void* const* d_in, const int* in_sizes, int n_in,
                              void* d_out, int out_size) {
    (void)in_sizes; (void)n_in; (void)out_size;
    const float* h    = (const float*)d_in[0];
    const int*   adj  = (const int*)d_in[1];
    const float* Win  = (const float*)d_in[2];
    const float* Wout = (const float*)d_in[3];
    const float* bias = (const float*)d_in[4];
    float* out = (float*)d_out;

    cudaFuncSetAttribute(ggnn_stage1, cudaFuncAttributeMaxDynamicSharedMemorySize,
                         S1_SMEM_W * 4);
    cudaFuncSetAttribute(ggnn_stage2, cudaFuncAttributeMaxDynamicSharedMemorySize,
                         SM2_W * 4);

    ggnn_stage1<<<2048, 128, S1_SMEM_W * 4>>>(h, Win, Wout);
    ggnn_stage2<<<dim3(8, 2, 32), 128, SM2_W * 4>>>(adj, bias, out);
}

// round 13
// speedup vs baseline: 1.1029x; 1.1029x over previous
#include <cuda_runtime.h>
#include <cuda_fp16.h>
#include <cstdint>

// GGNN message passing (SIMT mma.sync; tcgen05 not available on sm_103 target).
// Stage1 (tf32 MMA): G[j,dir,c,d] = sum_e h[j,e]*W[dir,c,d,e]; fp16x2 blob
//   [b][dir][ch][r][pd]: ch=j>>4, r = 8*((j&15)>>2) + ((j&15)&3) + 4a  (a=classpair),
//   word = (G_{c=2a}[d], G_{c=2a+1}[d]), pd = (d&7)*8+(d>>3).
// Stage2 (fp16 m16n8k16): out[b,i,dir*64+d] = sum_{j,c} 1[adjX==c]*G + bias.
//   K-map: f16x2 row m (in 16-k block) -> (jj=m&3, a=m>>2): thread tig's two A
//   words are classpairs (0,1)/(2,3) of ONE j -> one adj LDS + one u64 shift
//   yields both: X=0x3C00<<(16v); a_lo=lo32(X), a_hi=hi32(X). Exact one-hot.
//   dir=0: adjX=adj[b,i,j]; dir=1: adjX=adj[b,j,i].

__device__ uint32_t g_scratch[(size_t)8388608];  // 32 MB blob (f16x2 words)

__device__ __forceinline__ uint32_t f2tf(float x) {
    uint32_t r; asm("cvt.rna.tf32.f32 %0, %1;" : "=r"(r) : "f"(x)); return r;
}
__device__ __forceinline__ uint32_t pkh2(float lo, float hi) {
    __half2 p = __floats2half2_rn(lo, hi); return *(uint32_t*)&p;
}
__device__ __forceinline__ void mma8_tf32(float* d, uint32_t a0, uint32_t a1,
                                          uint32_t a2, uint32_t a3, uint32_t b0, uint32_t b1) {
    asm volatile("mma.sync.aligned.m16n8k8.row.col.f32.tf32.tf32.f32 "
                 "{%0,%1,%2,%3}, {%4,%5,%6,%7}, {%8,%9}, {%0,%1,%2,%3};"
                 : "+f"(d[0]), "+f"(d[1]), "+f"(d[2]), "+f"(d[3])
                 : "r"(a0), "r"(a1), "r"(a2), "r"(a3), "r"(b0), "r"(b1));
}
__device__ __forceinline__ void mma16_f16(float* d, uint32_t a0, uint32_t a1,
                                          uint32_t a2, uint32_t a3, uint32_t b0, uint32_t b1) {
    asm volatile("mma.sync.aligned.m16n8k16.row.col.f32.f16.f16.f32 "
                 "{%0,%1,%2,%3}, {%4,%5,%6,%7}, {%8,%9}, {%0,%1,%2,%3};"
                 : "+f"(d[0]), "+f"(d[1]), "+f"(d[2]), "+f"(d[3])
                 : "r"(a0), "r"(a1), "r"(a2), "r"(a3), "r"(b0), "r"(b1));
}
__device__ __forceinline__ void cpa16(uint32_t daddr, const void* gaddr) {
    asm volatile("cp.async.cg.shared.global [%0], [%1], 16;" :: "r"(daddr), "l"(gaddr));
}
__device__ __forceinline__ void cpa_commit() {
    asm volatile("cp.async.commit_group;" ::: "memory");
}
template <int N>
__device__ __forceinline__ void cpa_wait() {
    asm volatile("cp.async.wait_group %0;" :: "n"(N) : "memory");
}

// ---------------------------------------------------------------------------
// Stage 1: grid 2048 = (512 mtiles x 4 p4), 128 thr.
// smem: hs[64*68] + ws[64*136] = 13056 words = 52.2 KB.
// ---------------------------------------------------------------------------
#define S1_SMEM_W (4352 + 8704)

__global__ __launch_bounds__(128) void ggnn_stage1(const float* __restrict__ h,
                                                   const float* __restrict__ Win,
                                                   const float* __restrict__ Wout) {
    extern __shared__ uint32_t s1[];
    uint32_t* hs = s1;            // [row][e] stride 68
    uint32_t* ws = s1 + 4352;     // [e][n] stride 136

    const int bx = blockIdx.x;
    const int mtile = bx >> 2, p4 = bx & 3;
    const int t = threadIdx.x;
    const int warp = t >> 5, lane = t & 31;
    const int g = lane >> 2, tig = lane & 3;
    const int r0 = warp * 16 + g;

    // transpose W slice in-kernel: ws[e][n=t] = tf32(W[c][d][e])
    {
        const float* Wd = (p4 & 2) ? Wout : Win;
        const float4* src = (const float4*)(Wd + (size_t)(p4 & 1) * 8192
                                            + (t >> 6) * 4096 + (t & 63) * 64);
#pragma unroll
        for (int i = 0; i < 16; i++) {
            float4 v = src[i];
            int e = 4 * i;
            ws[(e + 0) * 136 + t] = f2tf(v.x);
            ws[(e + 1) * 136 + t] = f2tf(v.y);
            ws[(e + 2) * 136 + t] = f2tf(v.z);
            ws[(e + 3) * 136 + t] = f2tf(v.w);
        }
    }
    // stage h tile (tf32 bits)
    const float* hbase = h + (size_t)mtile * 4096;
#pragma unroll
    for (int q = 0; q < 8; q++) {
        int f4 = t + q * 128;
        int row = f4 >> 4, e4 = (f4 & 15) * 4;
        float4 v = *(const float4*)(hbase + row * 64 + e4);
        uint4 u = make_uint4(f2tf(v.x), f2tf(v.y), f2tf(v.z), f2tf(v.w));
        *(uint4*)(hs + row * 68 + e4) = u;
    }
    __syncthreads();

    float acc[16][4];
#pragma unroll
    for (int nt = 0; nt < 16; nt++)
#pragma unroll
        for (int k = 0; k < 4; k++) acc[nt][k] = 0.f;

#pragma unroll
    for (int ks = 0; ks < 8; ks++) {
        int e0 = ks * 8;
        uint32_t a0 = hs[r0 * 68 + e0 + tig];
        uint32_t a1 = hs[(r0 + 8) * 68 + e0 + tig];
        uint32_t a2 = hs[r0 * 68 + e0 + tig + 4];
        uint32_t a3 = hs[(r0 + 8) * 68 + e0 + tig + 4];
#pragma unroll
        for (int nt = 0; nt < 16; nt++) {
            uint32_t b0 = ws[(e0 + tig) * 136 + nt * 8 + g];
            uint32_t b1 = ws[(e0 + tig + 4) * 136 + nt * 8 + g];
            mma8_tf32(acc[nt], a0, a1, a2, a3, b0, b1);
        }
    }

    // blob store: row r = 8*(jl>>2) + 16*rb2 + (jl&3) + 4a, jl = g + 8*rb2
    const int b = mtile >> 4;
    const int ch = (mtile & 15) * 4 + warp;
    const int dir = p4 >> 1, a = p4 & 1;
    uint32_t* blob = g_scratch + ((size_t)(b * 2 + dir) << 17);
#pragma unroll
    for (int rb2 = 0; rb2 < 2; rb2++) {
        int r = 8 * (g >> 2) + 16 * rb2 + (g & 3) + 4 * a;
        uint32_t* dst = blob + ch * 2048 + r * 64 + 16 * tig;
        int i0 = rb2 * 2;
#pragma unroll
        for (int half = 0; half < 2; half++) {
#pragma unroll
            for (int grp = 0; grp < 2; grp++) {
                uint4 u;
                u.x = pkh2(acc[grp * 4 + 0][i0 + half], acc[grp * 4 + 8][i0 + half]);
                u.y = pkh2(acc[grp * 4 + 1][i0 + half], acc[grp * 4 + 9][i0 + half]);
                u.z = pkh2(acc[grp * 4 + 2][i0 + half], acc[grp * 4 + 10][i0 + half]);
                u.w = pkh2(acc[grp * 4 + 3][i0 + half], acc[grp * 4 + 11][i0 + half]);
                *(uint4*)(dst + half * 8 + grp * 4) = u;
            }
        }
    }
}

// ---------------------------------------------------------------------------
// Stage 2: grid (8 mtiles, 2 dirs, 32 b), 128 thr (4 warps x 32 rows), fp16 MMA.
// 2 buffers x (gs 32x68 + adj 2560) = 9472 words = 37.9 KB static smem.
// ---------------------------------------------------------------------------
#define GS2_W (32 * 68)                  // 2176
#define AS2_W 2560
#define BUF2_W (GS2_W + AS2_W)           // 4736
#define SM2_W (2 * BUF2_W)               // 9472 words

template <int DIR>
__device__ __forceinline__ void stage2_impl(uint32_t* sm,
                                            const int* __restrict__ adj,
                                            const float* __restrict__ bias,
                                            float* __restrict__ out) {
    const int mtile = blockIdx.x;
    const int b     = blockIdx.z;
    const int t = threadIdx.x;
    const int warp = t >> 5, lane = t & 31;
    const int g = lane >> 2, tig = lane & 3;
    const int mbase = mtile * 128;
    const int rw = warp * 32;

    const uint32_t* blob = g_scratch + ((size_t)(b * 2 + DIR) << 17);
    const int* adjb = adj + (size_t)b * 1048576;

    float acc[2][8][4];
#pragma unroll
    for (int rb = 0; rb < 2; rb++)
#pragma unroll
        for (int nt = 0; nt < 8; nt++)
#pragma unroll
            for (int k = 0; k < 4; k++) acc[rb][nt][k] = 0.f;

    auto issue = [&](int ch, int buf) {
        const int j0 = ch * 16;
        uint32_t gdst = (uint32_t)__cvta_generic_to_shared(sm + buf * BUF2_W);
        uint32_t adst = gdst + GS2_W * 4;
        const uint32_t* gsrc = blob + (size_t)ch * 2048;
#pragma unroll
        for (int q = 0; q < 4; q++) {            // 512 u4s of G
            int idx = t + q * 128;
            int kp = idx >> 4, pd4 = (idx & 15) * 4;
            cpa16(gdst + (kp * 68 + pd4) * 4, gsrc + kp * 64 + pd4);
        }
        if constexpr (DIR == 0) {                // [r][jj] stride 20
#pragma unroll
            for (int q = 0; q < 4; q++) {
                int idx = t + q * 128;
                int r = idx >> 2, c4 = (idx & 3) * 4;
                cpa16(adst + (r * 20 + c4) * 4, adjb + (size_t)(mbase + r) * 1024 + j0 + c4);
            }
        } else {                                 // [jj][r] stride 136
#pragma unroll
            for (int q = 0; q < 4; q++) {
                int idx = t + q * 128;
                int jj = idx >> 5, r4 = (idx & 31) * 4;
                cpa16(adst + (jj * 136 + r4) * 4, adjb + (size_t)(j0 + jj) * 1024 + mbase + r4);
            }
        }
        cpa_commit();
    };

    issue(0, 0);

#pragma unroll 1
    for (int ch = 0; ch < 64; ch++) {
        if (ch < 63) { issue(ch + 1, (ch + 1) & 1); cpa_wait<1>(); }
        else         { cpa_wait<0>(); }
        __syncthreads();

        const uint32_t* gs = sm + (ch & 1) * BUF2_W;
        const int* as_ = (const int*)(gs + GS2_W);
        constexpr int RS = DIR ? 1 : 20;
        constexpr int JS = DIR ? 136 : 1;

#pragma unroll
        for (int ks = 0; ks < 4; ks++) {
            const int jj = 4 * ks + tig;         // this thread's single j
            const int base = (rw + g) * RS + jj * JS;
            int v0 = as_[base];
            int v1 = as_[base + 8 * RS];
            int v2 = as_[base + 16 * RS];
            int v3 = as_[base + 24 * RS];
            // one u64 shift -> both classpair words (exact one-hot)
            uint64_t X0 = 0x3C00ULL << (v0 << 4);
            uint64_t X1 = 0x3C00ULL << (v1 << 4);
            uint64_t X2 = 0x3C00ULL << (v2 << 4);
            uint64_t X3 = 0x3C00ULL << (v3 << 4);
            uint32_t a00 = (uint32_t)X0, a02 = (uint32_t)(X0 >> 32);
            uint32_t a01 = (uint32_t)X1, a03 = (uint32_t)(X1 >> 32);
            uint32_t a10 = (uint32_t)X2, a12 = (uint32_t)(X2 >> 32);
            uint32_t a11 = (uint32_t)X3, a13 = (uint32_t)(X3 >> 32);

            const uint32_t* bp0 = gs + (8 * ks + tig) * 68 + 8 * g;   // a=0 rows
            const uint32_t* bp1 = bp0 + 4 * 68;                       // a=1 rows
            uint4 B0a = *(const uint4*)(bp0);
            uint4 B0b = *(const uint4*)(bp0 + 4);
            uint4 B1a = *(const uint4*)(bp1);
            uint4 B1b = *(const uint4*)(bp1 + 4);

            mma16_f16(acc[0][0], a00, a01, a02, a03, B0a.x, B1a.x);
            mma16_f16(acc[0][1], a00, a01, a02, a03, B0a.y, B1a.y);
            mma16_f16(acc[0][2], a00, a01, a02, a03, B0a.z, B1a.z);
            mma16_f16(acc[0][3], a00, a01, a02, a03, B0a.w, B1a.w);
            mma16_f16(acc[0][4], a00, a01, a02, a03, B0b.x, B1b.x);
            mma16_f16(acc[0][5], a00, a01, a02, a03, B0b.y, B1b.y);
            mma16_f16(acc[0][6], a00, a01, a02, a03, B0b.z, B1b.z);
            mma16_f16(acc[0][7], a00, a01, a02, a03, B0b.w, B1b.w);
            mma16_f16(acc[1][0], a10, a11, a12, a13, B0a.x, B1a.x);
            mma16_f16(acc[1][1], a10, a11, a12, a13, B0a.y, B1a.y);
            mma16_f16(acc[1][2], a10, a11, a12, a13, B0a.z, B1a.z);
            mma16_f16(acc[1][3], a10, a11, a12, a13, B0a.w, B1a.w);
            mma16_f16(acc[1][4], a10, a11, a12, a13, B0b.x, B1b.x);
            mma16_f16(acc[1][5], a10, a11, a12, a13, B0b.y, B1b.y);
            mma16_f16(acc[1][6], a10, a11, a12, a13, B0b.z, B1b.z);
            mma16_f16(acc[1][7], a10, a11, a12, a13, B0b.w, B1b.w);
        }
        __syncthreads();
    }

#pragma unroll
    for (int rb = 0; rb < 2; rb++) {
        const int i0 = mbase + rw + rb * 16 + g;
#pragma unroll
        for (int nt = 0; nt < 8; nt++) {
            int n = DIR * 64 + nt * 8 + tig * 2;
            float2 bv = *(const float2*)(bias + n);
            float* o0 = out + ((size_t)b * 1024 + i0) * 128 + n;
            float* o1 = out + ((size_t)b * 1024 + i0 + 8) * 128 + n;
            *(float2*)o0 = make_float2(acc[rb][nt][0] + bv.x, acc[rb][nt][1] + bv.y);
            *(float2*)o1 = make_float2(acc[rb][nt][2] + bv.x, acc[rb][nt][3] + bv.y);
        }
    }
}

__global__ __launch_bounds__(128, 4) void ggnn_stage2(const int* __restrict__ adj,
                                                      const float* __restrict__ bias,
                                                      float* __restrict__ out) {
    __shared__ uint32_t sm[SM2_W];
    if (blockIdx.y == 0) stage2_impl<0>(sm, adj, bias, out);
    else                 stage2_impl<1>(sm, adj, bias, out);
}

extern "C" void kernel_launch(void* const* d_in, const int* in_sizes, int n_in,
                              void* d_out, int out_size) {
    (void)in_sizes; (void)n_in; (void)out_size;
    const float* h    = (const float*)d_in[0];
    const int*   adj  = (const int*)d_in[1];
    const float* Win  = (const float*)d_in[2];
    const float* Wout = (const float*)d_in[3];
    const float* bias = (const float*)d_in[4];
    float* out = (float*)d_out;

    cudaFuncSetAttribute(ggnn_stage1, cudaFuncAttributeMaxDynamicSharedMemorySize,
                         S1_SMEM_W * 4);

    ggnn_stage1<<<2048, 128, S1_SMEM_W * 4>>>(h, Win, Wout);
    ggnn_stage2<<<dim3(8, 2, 32), 128>>>(adj, bias, out);
}